// round 1
// baseline (speedup 1.0000x reference)
#include <cuda_runtime.h>
#include <math.h>

#define B_SZ 2
#define SEQ 2048
#define H_Q 16
#define H_KV 4
#define DH 128
#define BM 64
#define BN 32
#define QS 129   /* sQ/sK row stride (floats): odd => conflict-free micro-tile reads */
#define VS 132   /* sV row stride: mult of 4 => float4-aligned, conflict-free PV reads */
#define PS 33    /* sP row stride */

#define SMEM_FLOATS (BM*QS + BN*QS + BN*VS + BM*PS)   /* 8256+4128+4224+2112 = 18720 */
#define SMEM_BYTES  (SMEM_FLOATS * 4)                 /* 74880 B */

// Scratch for normalized+RoPE'd Q and K, layout [b][h][s][d]
__device__ float g_q[(size_t)B_SZ * H_Q * SEQ * DH];
__device__ float g_k[(size_t)B_SZ * H_KV * SEQ * DH];

// ---------------------------------------------------------------------------
// Prep: per (b,s,h) row of 128: L2-normalize (eps clamp) then half-split RoPE.
// Input layout [b][s][h][d]; output layout [b][h][s][d].
// ---------------------------------------------------------------------------
__device__ __forceinline__ void prep_row(const float* __restrict__ x,
                                         float* __restrict__ y, int H) {
    int idx = blockIdx.x;            // b*SEQ*H + s*H + h
    int h = idx % H;
    int s = (idx / H) % SEQ;
    int b = idx / (H * SEQ);

    const float* xr = x + (size_t)idx * DH;
    int t = threadIdx.x;             // 0..127

    __shared__ float sx[DH];
    __shared__ float wss[4];

    float v = xr[t];
    sx[t] = v;
    float ss = v * v;
    #pragma unroll
    for (int o = 16; o; o >>= 1) ss += __shfl_xor_sync(0xffffffffu, ss, o);
    if ((t & 31) == 0) wss[t >> 5] = ss;
    __syncthreads();
    float tot = wss[0] + wss[1] + wss[2] + wss[3];
    float scale = 1.0f / fmaxf(sqrtf(tot), 1e-6f);

    int j = t & 63;
    // inv_freq[j] = 10000^(-j/64) = exp(-j * ln(10000)/64)
    float inv_freq = expf((float)j * -0.14391156831212785f);
    float sn, cs;
    sincosf((float)s * inv_freq, &sn, &cs);

    float x1 = sx[j] * scale;        // first half element
    float x2 = sx[j + 64] * scale;   // second half element
    float o = (t < 64) ? (x1 * cs + x2 * sn)    // y1 =  x1*cos + x2*sin
                       : (x2 * cs - x1 * sn);   // y2 = -x1*sin + x2*cos
    y[(((size_t)(b * H + h)) * SEQ + s) * DH + t] = o;
}

__global__ void prep_q_kernel(const float* __restrict__ x) { prep_row(x, g_q, H_Q); }
__global__ void prep_k_kernel(const float* __restrict__ x) { prep_row(x, g_k, H_KV); }

// ---------------------------------------------------------------------------
// Flash attention: one block per (b, h, 64-query tile). 128 threads.
// Thread (ty,tx), ty=t>>3 (16), tx=t&7 (8).
//   QK: thread computes 4x4 scores  (rows ty*4+r, cols tx*4+c)
//   PV: thread computes 4 rows x 16 cols (col = g*32 + tx*4 + c)
// ---------------------------------------------------------------------------
__global__ void __launch_bounds__(128, 2)
attn_kernel(const float* __restrict__ xv, float* __restrict__ out) {
    extern __shared__ float sm[];
    float* sQ = sm;
    float* sK = sQ + BM * QS;
    float* sV = sK + BN * QS;
    float* sP = sV + BN * VS;

    const int mt = (int)gridDim.x - 1 - (int)blockIdx.x;   // heavy tiles first
    const int bh = blockIdx.y;                              // b*16 + h
    const int b = bh >> 4, h = bh & 15;
    const int kvh = h >> 2;

    const int t  = threadIdx.x;
    const int ty = t >> 3, tx = t & 7;

    const float* Qb = g_q + ((size_t)bh * SEQ + (size_t)mt * BM) * DH;
    const float* Kb = g_k + ((size_t)(b * H_KV + kvh) * SEQ) * DH;
    const float* Vb = xv + (size_t)b * SEQ * (H_KV * DH) + kvh * DH;

    // Load Q tile (64x128) once, float4 global reads, scalar smem stores
    #pragma unroll
    for (int i = 0; i < 16; i++) {
        int li = t + i * 128;        // 0..2047 float4s
        int r = li >> 5, c4 = li & 31;
        float4 q4 = reinterpret_cast<const float4*>(Qb + (size_t)r * DH)[c4];
        float* d = sQ + r * QS + c4 * 4;
        d[0] = q4.x; d[1] = q4.y; d[2] = q4.z; d[3] = q4.w;
    }

    float acc[4][16];
    float m_[4], l_[4];
    #pragma unroll
    for (int r = 0; r < 4; r++) {
        m_[r] = -INFINITY; l_[r] = 0.0f;
        #pragma unroll
        for (int c = 0; c < 16; c++) acc[r][c] = 0.0f;
    }

    const int m_base = mt * BM;
    const int ntiles = (m_base + BM) / BN;     // causal: keys 0 .. m_base+63
    const float SCALE = 0.08838834764831845f;  // 1/sqrt(128)

    for (int kt = 0; kt < ntiles; kt++) {
        const int n0 = kt * BN;
        __syncthreads();   // prior iter done reading sK/sV

        // Load K tile (32x128) + V tile (32x128)
        #pragma unroll
        for (int i = 0; i < 8; i++) {
            int li = t + i * 128;    // 0..1023 float4s
            int r = li >> 5, c4 = li & 31;
            float4 k4 = reinterpret_cast<const float4*>(Kb + (size_t)(n0 + r) * DH)[c4];
            float* dk = sK + r * QS + c4 * 4;
            dk[0] = k4.x; dk[1] = k4.y; dk[2] = k4.z; dk[3] = k4.w;
            float4 v4 = reinterpret_cast<const float4*>(Vb + (size_t)(n0 + r) * (H_KV * DH))[c4];
            float* dv = sV + r * VS + c4 * 4;
            dv[0] = v4.x; dv[1] = v4.y; dv[2] = v4.z; dv[3] = v4.w;
        }
        __syncthreads();

        // ---- S = Q @ K^T (4x4 micro-tile per thread) ----
        float sc[4][4];
        #pragma unroll
        for (int r = 0; r < 4; r++)
            #pragma unroll
            for (int c = 0; c < 4; c++) sc[r][c] = 0.0f;

        const float* qb0 = sQ + (ty * 4) * QS;
        const float* kb0 = sK + (tx * 4) * QS;
        #pragma unroll 8
        for (int d = 0; d < DH; d++) {
            float a0 = qb0[d];
            float a1 = qb0[QS + d];
            float a2 = qb0[2 * QS + d];
            float a3 = qb0[3 * QS + d];
            float b0 = kb0[d];
            float b1 = kb0[QS + d];
            float b2 = kb0[2 * QS + d];
            float b3 = kb0[3 * QS + d];
            sc[0][0] += a0 * b0; sc[0][1] += a0 * b1; sc[0][2] += a0 * b2; sc[0][3] += a0 * b3;
            sc[1][0] += a1 * b0; sc[1][1] += a1 * b1; sc[1][2] += a1 * b2; sc[1][3] += a1 * b3;
            sc[2][0] += a2 * b0; sc[2][1] += a2 * b1; sc[2][2] += a2 * b2; sc[2][3] += a2 * b3;
            sc[3][0] += a3 * b0; sc[3][1] += a3 * b1; sc[3][2] += a3 * b2; sc[3][3] += a3 * b3;
        }

        // ---- mask + online softmax (row reductions across tx via shfl) ----
        #pragma unroll
        for (int r = 0; r < 4; r++) {
            int row = m_base + ty * 4 + r;
            float mx = -INFINITY;
            #pragma unroll
            for (int c = 0; c < 4; c++) {
                int col = n0 + tx * 4 + c;
                float v = (col <= row) ? sc[r][c] * SCALE : -INFINITY;
                sc[r][c] = v;
                mx = fmaxf(mx, v);
            }
            mx = fmaxf(mx, __shfl_xor_sync(0xffffffffu, mx, 1));
            mx = fmaxf(mx, __shfl_xor_sync(0xffffffffu, mx, 2));
            mx = fmaxf(mx, __shfl_xor_sync(0xffffffffu, mx, 4));
            float nm = fmaxf(m_[r], mx);           // finite after tile 0 for every row
            float alpha = __expf(m_[r] - nm);
            m_[r] = nm;
            float rs = 0.0f;
            #pragma unroll
            for (int c = 0; c < 4; c++) {
                float p = __expf(sc[r][c] - nm);   // masked -> exp(-inf)=0
                sc[r][c] = p;
                rs += p;
            }
            rs += __shfl_xor_sync(0xffffffffu, rs, 1);
            rs += __shfl_xor_sync(0xffffffffu, rs, 2);
            rs += __shfl_xor_sync(0xffffffffu, rs, 4);
            l_[r] = l_[r] * alpha + rs;
            #pragma unroll
            for (int c = 0; c < 16; c++) acc[r][c] *= alpha;
            #pragma unroll
            for (int c = 0; c < 4; c++) sP[(ty * 4 + r) * PS + tx * 4 + c] = sc[r][c];
        }
        __syncwarp();   // P rows are produced/consumed within one warp (same ty group)

        // ---- acc += P @ V (4 rows x 16 cols per thread) ----
        #pragma unroll 4
        for (int n = 0; n < BN; n++) {
            float p0 = sP[(ty * 4 + 0) * PS + n];
            float p1 = sP[(ty * 4 + 1) * PS + n];
            float p2 = sP[(ty * 4 + 2) * PS + n];
            float p3 = sP[(ty * 4 + 3) * PS + n];
            #pragma unroll
            for (int g = 0; g < 4; g++) {
                float4 v4 = *reinterpret_cast<const float4*>(sV + n * VS + g * 32 + tx * 4);
                acc[0][g * 4 + 0] += p0 * v4.x; acc[0][g * 4 + 1] += p0 * v4.y;
                acc[0][g * 4 + 2] += p0 * v4.z; acc[0][g * 4 + 3] += p0 * v4.w;
                acc[1][g * 4 + 0] += p1 * v4.x; acc[1][g * 4 + 1] += p1 * v4.y;
                acc[1][g * 4 + 2] += p1 * v4.z; acc[1][g * 4 + 3] += p1 * v4.w;
                acc[2][g * 4 + 0] += p2 * v4.x; acc[2][g * 4 + 1] += p2 * v4.y;
                acc[2][g * 4 + 2] += p2 * v4.z; acc[2][g * 4 + 3] += p2 * v4.w;
                acc[3][g * 4 + 0] += p3 * v4.x; acc[3][g * 4 + 1] += p3 * v4.y;
                acc[3][g * 4 + 2] += p3 * v4.z; acc[3][g * 4 + 3] += p3 * v4.w;
            }
        }
    }

    // ---- epilogue: normalize by l, write [b][s][h*128+d] ----
    #pragma unroll
    for (int r = 0; r < 4; r++) {
        float inv = 1.0f / l_[r];
        int row = m_base + ty * 4 + r;
        float* orow = out + ((size_t)(b * SEQ + row)) * (H_Q * DH) + h * DH;
        #pragma unroll
        for (int g = 0; g < 4; g++) {
            float4 o4;
            o4.x = acc[r][g * 4 + 0] * inv;
            o4.y = acc[r][g * 4 + 1] * inv;
            o4.z = acc[r][g * 4 + 2] * inv;
            o4.w = acc[r][g * 4 + 3] * inv;
            reinterpret_cast<float4*>(orow)[g * 8 + tx] = o4;
        }
    }
}

extern "C" void kernel_launch(void* const* d_in, const int* in_sizes, int n_in,
                              void* d_out, int out_size) {
    (void)in_sizes; (void)n_in; (void)out_size;
    const float* xq = (const float*)d_in[0];
    const float* xk = (const float*)d_in[1];
    const float* xv = (const float*)d_in[2];
    float* out = (float*)d_out;

    prep_q_kernel<<<B_SZ * SEQ * H_Q, 128>>>(xq);
    prep_k_kernel<<<B_SZ * SEQ * H_KV, 128>>>(xk);

    cudaFuncSetAttribute(attn_kernel, cudaFuncAttributeMaxDynamicSharedMemorySize,
                         SMEM_BYTES);
    dim3 grid(SEQ / BM, B_SZ * H_Q);
    attn_kernel<<<grid, 128, SMEM_BYTES>>>(xv, out);
}

// round 4
// speedup vs baseline: 3.9741x; 3.9741x over previous
#include <cuda_runtime.h>
#include <cuda_bf16.h>
#include <math.h>
#include <stdint.h>

#define SEQ 2048
#define HQ 16
#define HKV 4
#define DH 128
#define BM 128
#define BN 64
#define NTHREADS 256

#define SM_Q 0
#define SM_K 32768
#define SM_V 49152
#define OSTRIDE 132
#define SM_L (BM * OSTRIDE * 4)          /* 67584: row-l array after sO staging */
#define SMEM_BYTES (SM_L + BM * 4)       /* 68096 */
#define ATTN_SCALE 0.08838834764831845f  /* 1/sqrt(128) */

// ---------------------------------------------------------------------------
// Globals: bf16 prepped Q/K/V, RoPE table, fp32 causal prefix-sum of V
// ---------------------------------------------------------------------------
__device__ __align__(256) __nv_bfloat16 g_q[(size_t)2 * HQ * SEQ * DH];
__device__ __align__(256) __nv_bfloat16 g_k[(size_t)2 * HKV * SEQ * DH];
__device__ __align__(256) __nv_bfloat16 g_v[(size_t)2 * HKV * SEQ * DH];
__device__ float2 g_rope[SEQ * 64];
__device__ float g_psum[2 * HKV * 16 * DH];
__device__ float g_coff[2 * HKV * 16 * DH];
__device__ float g_vpre[(size_t)2 * HKV * SEQ * DH];   // inclusive prefix of V

// ---------------------------------------------------------------------------
// PTX helpers (base sm_100 ISA: ldmatrix + mma.sync only)
// ---------------------------------------------------------------------------
__device__ __forceinline__ uint32_t smem_to_u32(const void* p) {
    uint32_t a;
    asm("{ .reg .u64 t; cvta.to.shared.u64 t, %1; cvt.u32.u64 %0, t; }" : "=r"(a) : "l"(p));
    return a;
}
__device__ __forceinline__ void ldsm4(uint32_t* r, uint32_t addr) {
    asm volatile("ldmatrix.sync.aligned.m8n8.x4.shared.b16 {%0,%1,%2,%3}, [%4];"
                 : "=r"(r[0]), "=r"(r[1]), "=r"(r[2]), "=r"(r[3]) : "r"(addr));
}
__device__ __forceinline__ void ldsm4t(uint32_t* r, uint32_t addr) {
    asm volatile("ldmatrix.sync.aligned.m8n8.x4.trans.shared.b16 {%0,%1,%2,%3}, [%4];"
                 : "=r"(r[0]), "=r"(r[1]), "=r"(r[2]), "=r"(r[3]) : "r"(addr));
}
__device__ __forceinline__ void mma_bf16(float* c, const uint32_t* a,
                                         uint32_t b0, uint32_t b1) {
    asm volatile("mma.sync.aligned.m16n8k16.row.col.f32.bf16.bf16.f32 "
                 "{%0,%1,%2,%3}, {%4,%5,%6,%7}, {%8,%9}, {%0,%1,%2,%3};"
                 : "+f"(c[0]), "+f"(c[1]), "+f"(c[2]), "+f"(c[3])
                 : "r"(a[0]), "r"(a[1]), "r"(a[2]), "r"(a[3]), "r"(b0), "r"(b1));
}
// Swizzled byte offset in a [rows][256B] bf16 tile (conflict-free for ldmatrix)
__device__ __forceinline__ uint32_t sw(int row, int cb) {
    return (uint32_t)(row * 256 + (cb ^ ((row & 7) << 4)));
}

// ---------------------------------------------------------------------------
// Prep kernels
// ---------------------------------------------------------------------------
__global__ void rope_fill_kernel() {
    int s = blockIdx.x, j = threadIdx.x;                 // 2048 x 64
    float inv_freq = exp2f((float)j * (-13.287712379549449f / 64.0f)); // 10000^(-j/64)
    float sn, cs;
    sincosf((float)s * inv_freq, &sn, &cs);
    g_rope[s * 64 + j] = make_float2(cs, sn);
}

__device__ __forceinline__ void prep_row(const float* __restrict__ x,
                                         __nv_bfloat16* __restrict__ y, int H) {
    int idx = blockIdx.x;            // b*SEQ*H + s*H + h
    int h = idx % H;
    int s = (idx / H) % SEQ;
    int b = idx / (H * SEQ);
    const float* xr = x + (size_t)idx * DH;
    int t = threadIdx.x;             // 0..127

    __shared__ float sx[DH];
    __shared__ float wss[4];
    float v = xr[t];
    sx[t] = v;
    float ss = v * v;
    #pragma unroll
    for (int o = 16; o; o >>= 1) ss += __shfl_xor_sync(0xffffffffu, ss, o);
    if ((t & 31) == 0) wss[t >> 5] = ss;
    __syncthreads();
    float tot = wss[0] + wss[1] + wss[2] + wss[3];
    float scale = 1.0f / fmaxf(sqrtf(tot), 1e-6f);

    int j = t & 63;
    float2 cssn = g_rope[s * 64 + j];
    float x1 = sx[j] * scale;
    float x2 = sx[j + 64] * scale;
    float o = (t < 64) ? (x1 * cssn.x + x2 * cssn.y)
                       : (x2 * cssn.x - x1 * cssn.y);
    y[(((size_t)(b * H + h)) * SEQ + s) * DH + t] = __float2bfloat16(o);
}
__global__ void prep_q_kernel(const float* __restrict__ x) { prep_row(x, g_q, HQ); }
__global__ void prep_k_kernel(const float* __restrict__ x) { prep_row(x, g_k, HKV); }

__global__ void prep_v_kernel(const float* __restrict__ x) {
    int idx = blockIdx.x;            // b*SEQ*HKV + s*HKV + h
    int h = idx % HKV;
    int s = (idx / HKV) % SEQ;
    int b = idx / (HKV * SEQ);
    int t = threadIdx.x;
    g_v[(((size_t)(b * HKV + h)) * SEQ + s) * DH + t] =
        __float2bfloat16(x[(size_t)idx * DH + t]);
}

// --- fp32 causal prefix-sum of V over s, per (b, kvh, d). 3-phase scan. ---
__global__ void psum_kernel(const float* __restrict__ xv) {
    int blk = blockIdx.x;            // b*64 + kvh*16 + chunk
    int chunk = blk & 15, kvh = (blk >> 4) & 3, b = blk >> 6;
    int d = threadIdx.x;
    const float* p = xv + ((size_t)b * SEQ + chunk * 128) * (HKV * DH) + kvh * DH + d;
    float s = 0.f;
    #pragma unroll 8
    for (int i = 0; i < 128; i++) s += p[(size_t)i * (HKV * DH)];
    g_psum[blk * DH + d] = s;
}
__global__ void scan_kernel() {
    int blk = blockIdx.x;            // b*4 + kvh (8 blocks)
    int d = threadIdx.x;
    float run = 0.f;
    #pragma unroll
    for (int c = 0; c < 16; c++) {
        int idx = (blk * 16 + c) * DH + d;
        g_coff[idx] = run;
        run += g_psum[idx];
    }
}
__global__ void vpre_kernel(const float* __restrict__ xv) {
    int blk = blockIdx.x;            // b*64 + kvh*16 + chunk
    int chunk = blk & 15, kvh = (blk >> 4) & 3, b = blk >> 6;
    int d = threadIdx.x;
    const float* p = xv + ((size_t)b * SEQ + chunk * 128) * (HKV * DH) + kvh * DH + d;
    float acc = g_coff[blk * DH + d];
    float* o = g_vpre + ((size_t)(b * HKV + kvh) * SEQ + chunk * 128) * DH + d;
    #pragma unroll 8
    for (int i = 0; i < 128; i++) {
        acc += p[(size_t)i * (HKV * DH)];
        o[(size_t)i * DH] = acc;
    }
}

// ---------------------------------------------------------------------------
// bf16 mma.sync flash attention with p = 1 + u decomposition.
// O_num[r] = prefixV[r] (fp32 exact) + mma(Sigma u_k v_k);  l = (r+1) + Sigma u.
// CTA: 256 thr (8 warps), BM=128 q-rows (16/warp), BN=64 keys/tile.
// ---------------------------------------------------------------------------
__global__ void __launch_bounds__(NTHREADS, 1)
attn_kernel(float* __restrict__ out) {
    extern __shared__ char smem[];
    const uint32_t sb = smem_to_u32(smem);
    const int t = threadIdx.x;
    const int w = t >> 5, lane = t & 31;
    const int g = lane >> 2, j = lane & 3;
    const int i8 = lane & 7, sel = lane >> 3;

    const int mt = (int)gridDim.x - 1 - (int)blockIdx.x;   // heavy tiles first
    const int bh = blockIdx.y;
    const int b = bh >> 4, h = bh & 15;
    const int kvh = h >> 2;
    const int m_base = mt * BM;
    const int ntiles = 2 * mt + 2;

    const __nv_bfloat16* Qg = g_q + ((size_t)bh * SEQ + m_base) * DH;
    const __nv_bfloat16* Kg = g_k + ((size_t)(b * HKV + kvh) * SEQ) * DH;
    const __nv_bfloat16* Vg = g_v + ((size_t)(b * HKV + kvh) * SEQ) * DH;

    // ---- load Q tile (128 rows x 256B), swizzled ----
    #pragma unroll
    for (int i = 0; i < 8; i++) {
        int c = t + i * 256;
        int row = c >> 4, cb = (c & 15) * 16;
        *reinterpret_cast<uint4*>(smem + SM_Q + sw(row, cb)) =
            reinterpret_cast<const uint4*>(Qg)[c];
    }
    __syncthreads();

    // ---- Q fragments to registers ----
    uint32_t aq[8][4];
    {
        int qrow = w * 16 + i8 + ((sel & 1) << 3);
        #pragma unroll
        for (int kc = 0; kc < 8; kc++) {
            int db = kc * 32 + ((sel >> 1) << 4);
            ldsm4(aq[kc], sb + SM_Q + sw(qrow, db));
        }
    }

    float O[16][4];
    #pragma unroll
    for (int f = 0; f < 16; f++) {
        O[f][0] = 0.f; O[f][1] = 0.f; O[f][2] = 0.f; O[f][3] = 0.f;
    }
    float su_lo = 0.f, su_hi = 0.f;        // Sigma u per row
    const int row_lo = m_base + w * 16 + g;
    const int row_hi = row_lo + 8;
    const int wrow_min = m_base + w * 16;
    const int wrow_max = wrow_min + 15;

    for (int kt = 0; kt < ntiles; kt++) {
        const int n0 = kt * BN;
        __syncthreads();

        // ---- load K + V tiles (64 rows x 256B each), swizzled ----
        #pragma unroll
        for (int i = 0; i < 4; i++) {
            int c = t + i * 256;
            int row = c >> 4, cb = (c & 15) * 16;
            *reinterpret_cast<uint4*>(smem + SM_K + sw(row, cb)) =
                reinterpret_cast<const uint4*>(Kg + (size_t)n0 * DH)[c];
            *reinterpret_cast<uint4*>(smem + SM_V + sw(row, cb)) =
                reinterpret_cast<const uint4*>(Vg + (size_t)n0 * DH)[c];
        }
        __syncthreads();

        if (n0 > wrow_max) continue;   // warp fully masked

        // ---- S = Q K^T ----
        float S[8][4];
        #pragma unroll
        for (int f = 0; f < 8; f++) {
            S[f][0] = 0.f; S[f][1] = 0.f; S[f][2] = 0.f; S[f][3] = 0.f;
        }
        #pragma unroll
        for (int kc = 0; kc < 8; kc++) {
            int db = kc * 32 + ((sel & 1) << 4);
            #pragma unroll
            for (int np = 0; np < 4; np++) {
                uint32_t kb[4];
                int krow = np * 16 + i8 + ((sel >> 1) << 3);
                ldsm4(kb, sb + SM_K + sw(krow, db));
                mma_bf16(S[np * 2],     aq[kc], kb[0], kb[1]);
                mma_bf16(S[np * 2 + 1], aq[kc], kb[2], kb[3]);
            }
        }

        // ---- u = exp(s*scale) - 1, mask -> 0, bf16 A-fragments ----
        const bool diag = (n0 + BN - 1 > wrow_min);
        uint32_t pA[8], pB[8];
        #pragma unroll
        for (int nf = 0; nf < 8; nf++) {
            int colb = n0 + nf * 8 + 2 * j;
            float u0 = __expf(S[nf][0] * ATTN_SCALE) - 1.0f;
            float u1 = __expf(S[nf][1] * ATTN_SCALE) - 1.0f;
            float u2 = __expf(S[nf][2] * ATTN_SCALE) - 1.0f;
            float u3 = __expf(S[nf][3] * ATTN_SCALE) - 1.0f;
            if (diag) {
                if (colb     > row_lo) u0 = 0.f;
                if (colb + 1 > row_lo) u1 = 0.f;
                if (colb     > row_hi) u2 = 0.f;
                if (colb + 1 > row_hi) u3 = 0.f;
            }
            __nv_bfloat162 ba = __floats2bfloat162_rn(u0, u1);
            __nv_bfloat162 bb = __floats2bfloat162_rn(u2, u3);
            su_lo += __bfloat162float(ba.x) + __bfloat162float(ba.y);
            su_hi += __bfloat162float(bb.x) + __bfloat162float(bb.y);
            pA[nf] = *reinterpret_cast<uint32_t*>(&ba);
            pB[nf] = *reinterpret_cast<uint32_t*>(&bb);
        }

        // ---- O += u V ----
        #pragma unroll
        for (int kc2 = 0; kc2 < 4; kc2++) {
            uint32_t pa[4] = {pA[2 * kc2], pB[2 * kc2], pA[2 * kc2 + 1], pB[2 * kc2 + 1]};
            int vrow = kc2 * 16 + i8 + ((sel & 1) << 3);
            #pragma unroll
            for (int dp = 0; dp < 8; dp++) {
                uint32_t vb[4];
                int db = dp * 32 + ((sel >> 1) << 4);
                ldsm4t(vb, sb + SM_V + sw(vrow, db));
                mma_bf16(O[dp * 2],     pa, vb[0], vb[1]);
                mma_bf16(O[dp * 2 + 1], pa, vb[2], vb[3]);
            }
        }
    }

    __syncthreads();   // done with K/V/Q smem before staging reuse

    // ---- epilogue: l = (r+1) + Sigma u; stage mma part; fused final store ----
    su_lo += __shfl_xor_sync(0xffffffffu, su_lo, 1);
    su_lo += __shfl_xor_sync(0xffffffffu, su_lo, 2);
    su_hi += __shfl_xor_sync(0xffffffffu, su_hi, 1);
    su_hi += __shfl_xor_sync(0xffffffffu, su_hi, 2);

    float* sO = reinterpret_cast<float*>(smem);
    float* sL = reinterpret_cast<float*>(smem + SM_L);
    if (j == 0) {
        sL[w * 16 + g]     = (float)(row_lo + 1) + su_lo;
        sL[w * 16 + g + 8] = (float)(row_hi + 1) + su_hi;
    }
    #pragma unroll
    for (int f = 0; f < 16; f++) {
        int colb = f * 8 + 2 * j;
        sO[(w * 16 + g)     * OSTRIDE + colb]     = O[f][0];
        sO[(w * 16 + g)     * OSTRIDE + colb + 1] = O[f][1];
        sO[(w * 16 + g + 8) * OSTRIDE + colb]     = O[f][2];
        sO[(w * 16 + g + 8) * OSTRIDE + colb + 1] = O[f][3];
    }
    __syncthreads();

    {
        int cc = t & 127, rh = t >> 7;
        const float* preb = g_vpre + ((size_t)(b * HKV + kvh) * SEQ + m_base) * DH;
        size_t obase = ((size_t)(b * SEQ + m_base)) * (HQ * DH) + (size_t)h * DH;
        #pragma unroll 4
        for (int i = 0; i < 64; i++) {
            int rr = i * 2 + rh;
            float inv = 1.0f / sL[rr];
            out[obase + (size_t)rr * (HQ * DH) + cc] =
                (sO[rr * OSTRIDE + cc] + preb[(size_t)rr * DH + cc]) * inv;
        }
    }
}

// ---------------------------------------------------------------------------
extern "C" void kernel_launch(void* const* d_in, const int* in_sizes, int n_in,
                              void* d_out, int out_size) {
    (void)in_sizes; (void)n_in; (void)out_size;
    const float* xq = (const float*)d_in[0];
    const float* xk = (const float*)d_in[1];
    const float* xv = (const float*)d_in[2];
    float* out = (float*)d_out;

    rope_fill_kernel<<<SEQ, 64>>>();
    prep_q_kernel<<<2 * SEQ * HQ, 128>>>(xq);
    prep_k_kernel<<<2 * SEQ * HKV, 128>>>(xk);
    prep_v_kernel<<<2 * SEQ * HKV, 128>>>(xv);
    psum_kernel<<<2 * HKV * 16, DH>>>(xv);
    scan_kernel<<<2 * HKV, DH>>>();
    vpre_kernel<<<2 * HKV * 16, DH>>>(xv);

    cudaFuncSetAttribute(attn_kernel, cudaFuncAttributeMaxDynamicSharedMemorySize,
                         SMEM_BYTES);
    dim3 grid(SEQ / BM, 2 * HQ);
    attn_kernel<<<grid, NTHREADS, SMEM_BYTES>>>(out);
}

// round 6
// speedup vs baseline: 4.8360x; 1.2169x over previous
#include <cuda_runtime.h>
#include <cuda_bf16.h>
#include <math.h>
#include <stdint.h>

#define SEQ 2048
#define HQ 16
#define HKV 4
#define DH 128
#define BM 128
#define BN 64
#define NTHREADS 256

// smem layout (bytes): Q 32KB, K/V double-buffered 16KB each
#define SM_Q 0
#define SM_K0 32768
#define SM_K1 49152
#define SM_V0 65536
#define SM_V1 81920
#define SMEM_BYTES 98304
#define OSTRIDE 132
#define SM_L (BM * OSTRIDE * 4)          /* 67584 < 98304: l array after sO staging */
#define ATTN_SCALE 0.08838834764831845f  /* 1/sqrt(128) */

// ---------------------------------------------------------------------------
// Globals: bf16 prepped Q/K/V, RoPE table, fp32 causal prefix-sum of V
// ---------------------------------------------------------------------------
__device__ __align__(256) __nv_bfloat16 g_q[(size_t)2 * HQ * SEQ * DH];
__device__ __align__(256) __nv_bfloat16 g_k[(size_t)2 * HKV * SEQ * DH];
__device__ __align__(256) __nv_bfloat16 g_v[(size_t)2 * HKV * SEQ * DH];
__device__ __align__(16) float2 g_rope[SEQ * 64];
__device__ float g_psum[2 * HKV * 16 * DH];
__device__ float g_coff[2 * HKV * 16 * DH];
__device__ float g_vpre[(size_t)2 * HKV * SEQ * DH];   // inclusive prefix of V

// ---------------------------------------------------------------------------
// PTX helpers (base ISA: ldmatrix, mma.sync, cp.async)
// ---------------------------------------------------------------------------
__device__ __forceinline__ uint32_t smem_to_u32(const void* p) {
    uint32_t a;
    asm("{ .reg .u64 t; cvta.to.shared.u64 t, %1; cvt.u32.u64 %0, t; }" : "=r"(a) : "l"(p));
    return a;
}
__device__ __forceinline__ void ldsm4(uint32_t* r, uint32_t addr) {
    asm volatile("ldmatrix.sync.aligned.m8n8.x4.shared.b16 {%0,%1,%2,%3}, [%4];"
                 : "=r"(r[0]), "=r"(r[1]), "=r"(r[2]), "=r"(r[3]) : "r"(addr));
}
__device__ __forceinline__ void ldsm4t(uint32_t* r, uint32_t addr) {
    asm volatile("ldmatrix.sync.aligned.m8n8.x4.trans.shared.b16 {%0,%1,%2,%3}, [%4];"
                 : "=r"(r[0]), "=r"(r[1]), "=r"(r[2]), "=r"(r[3]) : "r"(addr));
}
__device__ __forceinline__ void mma_bf16(float* c, const uint32_t* a,
                                         uint32_t b0, uint32_t b1) {
    asm volatile("mma.sync.aligned.m16n8k16.row.col.f32.bf16.bf16.f32 "
                 "{%0,%1,%2,%3}, {%4,%5,%6,%7}, {%8,%9}, {%0,%1,%2,%3};"
                 : "+f"(c[0]), "+f"(c[1]), "+f"(c[2]), "+f"(c[3])
                 : "r"(a[0]), "r"(a[1]), "r"(a[2]), "r"(a[3]), "r"(b0), "r"(b1));
}
__device__ __forceinline__ void cpa16(uint32_t dst, const void* src) {
    asm volatile("cp.async.cg.shared.global [%0], [%1], 16;" :: "r"(dst), "l"(src));
}
#define CPA_COMMIT() asm volatile("cp.async.commit_group;" ::: "memory")
#define CPA_WAIT(n)  asm volatile("cp.async.wait_group %0;" :: "n"(n) : "memory")

// Swizzled byte offset in a [rows][256B] bf16 tile (conflict-free for ldmatrix)
__device__ __forceinline__ uint32_t sw(int row, int cb) {
    return (uint32_t)(row * 256 + (cb ^ ((row & 7) << 4)));
}
// expm1 for |x| <= 0.0884: Horner degree 4, abs err < 5e-8
__device__ __forceinline__ float expm1s(float x) {
    float p = fmaf(x, 0.041666668f, 0.16666667f);
    p = fmaf(x, p, 0.5f);
    p = fmaf(x, p, 1.0f);
    return x * p;
}

// ---------------------------------------------------------------------------
// Prep kernels (warp-per-row, float4, shfl-only)
// ---------------------------------------------------------------------------
__global__ void rope_fill_kernel() {
    int s = blockIdx.x, j = threadIdx.x;                 // 2048 x 64
    float inv_freq = exp2f((float)j * (-13.287712379549449f / 64.0f)); // 10000^(-j/64)
    float sn, cs;
    sincosf((float)s * inv_freq, &sn, &cs);
    g_rope[s * 64 + j] = make_float2(cs, sn);
}

__device__ __forceinline__ void prep_row_v(const float* __restrict__ x,
                                           __nv_bfloat16* __restrict__ y, int H) {
    const int wid = threadIdx.x >> 5, lane = threadIdx.x & 31;
    const int idx = blockIdx.x * 4 + wid;                // b*SEQ*H + s*H + h
    const int h = idx % H;
    const int s = (idx / H) % SEQ;
    const int b = idx / (H * SEQ);

    float4 v = reinterpret_cast<const float4*>(x + (size_t)idx * DH)[lane];
    float ss = v.x * v.x + v.y * v.y + v.z * v.z + v.w * v.w;
    #pragma unroll
    for (int o = 16; o; o >>= 1) ss += __shfl_xor_sync(0xffffffffu, ss, o);
    float scale = 1.0f / fmaxf(sqrtf(ss), 1e-6f);

    float px = __shfl_xor_sync(0xffffffffu, v.x, 16);
    float py = __shfl_xor_sync(0xffffffffu, v.y, 16);
    float pz = __shfl_xor_sync(0xffffffffu, v.z, 16);
    float pw = __shfl_xor_sync(0xffffffffu, v.w, 16);

    int j0 = 4 * (lane & 15);
    const float4* rp = reinterpret_cast<const float4*>(g_rope + s * 64 + j0);
    float4 r01 = rp[0];   // cos0,sin0,cos1,sin1
    float4 r23 = rp[1];

    float o0, o1, o2, o3;
    if (lane < 16) {       // y1 = x1*cos + x2*sin
        o0 = (v.x * r01.x + px * r01.y) * scale;
        o1 = (v.y * r01.z + py * r01.w) * scale;
        o2 = (v.z * r23.x + pz * r23.y) * scale;
        o3 = (v.w * r23.z + pw * r23.w) * scale;
    } else {               // y2 = x2*cos - x1*sin
        o0 = (v.x * r01.x - px * r01.y) * scale;
        o1 = (v.y * r01.z - py * r01.w) * scale;
        o2 = (v.z * r23.x - pz * r23.y) * scale;
        o3 = (v.w * r23.z - pw * r23.w) * scale;
    }
    __nv_bfloat162 ba = __floats2bfloat162_rn(o0, o1);
    __nv_bfloat162 bb = __floats2bfloat162_rn(o2, o3);
    uint2 pk = make_uint2(*reinterpret_cast<uint32_t*>(&ba),
                          *reinterpret_cast<uint32_t*>(&bb));
    *reinterpret_cast<uint2*>(y + (((size_t)(b * H + h)) * SEQ + s) * DH + 4 * lane) = pk;
}
__global__ void prep_q_kernel(const float* __restrict__ x) { prep_row_v(x, g_q, HQ); }
__global__ void prep_k_kernel(const float* __restrict__ x) { prep_row_v(x, g_k, HKV); }

__global__ void prep_v_kernel(const float* __restrict__ x) {
    const int wid = threadIdx.x >> 5, lane = threadIdx.x & 31;
    const int idx = blockIdx.x * 8 + wid;                // b*SEQ*HKV + s*HKV + h
    const int h = idx % HKV;
    const int s = (idx / HKV) % SEQ;
    const int b = idx / (HKV * SEQ);
    float4 v = reinterpret_cast<const float4*>(x + (size_t)idx * DH)[lane];
    __nv_bfloat162 ba = __floats2bfloat162_rn(v.x, v.y);
    __nv_bfloat162 bb = __floats2bfloat162_rn(v.z, v.w);
    uint2 pk = make_uint2(*reinterpret_cast<uint32_t*>(&ba),
                          *reinterpret_cast<uint32_t*>(&bb));
    *reinterpret_cast<uint2*>(g_v + (((size_t)(b * HKV + h)) * SEQ + s) * DH + 4 * lane) = pk;
}

// --- fp32 causal prefix-sum of V over s, per (b, kvh, d). 3-phase scan. ---
__global__ void psum_kernel(const float* __restrict__ xv) {
    int blk = blockIdx.x;            // b*64 + kvh*16 + chunk
    int chunk = blk & 15, kvh = (blk >> 4) & 3, b = blk >> 6;
    int d = threadIdx.x;
    const float* p = xv + ((size_t)b * SEQ + chunk * 128) * (HKV * DH) + kvh * DH + d;
    float s = 0.f;
    #pragma unroll 8
    for (int i = 0; i < 128; i++) s += p[(size_t)i * (HKV * DH)];
    g_psum[blk * DH + d] = s;
}
__global__ void scan_kernel() {
    int blk = blockIdx.x;            // b*4 + kvh
    int d = threadIdx.x;
    float run = 0.f;
    #pragma unroll
    for (int c = 0; c < 16; c++) {
        int idx = (blk * 16 + c) * DH + d;
        g_coff[idx] = run;
        run += g_psum[idx];
    }
}
__global__ void vpre_kernel(const float* __restrict__ xv) {
    int blk = blockIdx.x;            // b*64 + kvh*16 + chunk
    int chunk = blk & 15, kvh = (blk >> 4) & 3, b = blk >> 6;
    int d = threadIdx.x;
    const float* p = xv + ((size_t)b * SEQ + chunk * 128) * (HKV * DH) + kvh * DH + d;
    float acc = g_coff[blk * DH + d];
    float* o = g_vpre + ((size_t)(b * HKV + kvh) * SEQ + chunk * 128) * DH + d;
    #pragma unroll 8
    for (int i = 0; i < 128; i++) {
        acc += p[(size_t)i * (HKV * DH)];
        o[(size_t)i * DH] = acc;
    }
}

// ---------------------------------------------------------------------------
// bf16 mma.sync flash attention, p = 1 + u, cp.async double-buffered K/V.
// CTA: 256 thr (8 warps), BM=128 q-rows (16/warp), BN=64 keys/tile, 2 CTAs/SM.
// ---------------------------------------------------------------------------
__global__ void __launch_bounds__(NTHREADS, 2)
attn_kernel(float* __restrict__ out) {
    extern __shared__ char smem[];
    const uint32_t sb = smem_to_u32(smem);
    const int t = threadIdx.x;
    const int w = t >> 5, lane = t & 31;
    const int g = lane >> 2, j = lane & 3;
    const int i8 = lane & 7, sel = lane >> 3;

    const int mt = (int)gridDim.x - 1 - (int)blockIdx.x;   // heavy tiles first
    const int bh = blockIdx.y;
    const int b = bh >> 4, h = bh & 15;
    const int kvh = h >> 2;
    const int m_base = mt * BM;
    const int ntiles = 2 * mt + 2;

    const __nv_bfloat16* Qg = g_q + ((size_t)bh * SEQ + m_base) * DH;
    const __nv_bfloat16* Kg = g_k + ((size_t)(b * HKV + kvh) * SEQ) * DH;
    const __nv_bfloat16* Vg = g_v + ((size_t)(b * HKV + kvh) * SEQ) * DH;

    const uint32_t smk[2] = {sb + SM_K0, sb + SM_K1};
    const uint32_t smv[2] = {sb + SM_V0, sb + SM_V1};

    // prologue: async-issue K/V tile 0, then load Q while it flies
    {
        #pragma unroll
        for (int i = 0; i < 4; i++) {
            int c = t + i * 256;
            int row = c >> 4, cb = (c & 15) * 16;
            cpa16(smk[0] + sw(row, cb), (const char*)Kg + c * 16);
            cpa16(smv[0] + sw(row, cb), (const char*)Vg + c * 16);
        }
        CPA_COMMIT();
    }
    #pragma unroll
    for (int i = 0; i < 8; i++) {
        int c = t + i * 256;
        int row = c >> 4, cb = (c & 15) * 16;
        *reinterpret_cast<uint4*>(smem + SM_Q + sw(row, cb)) =
            reinterpret_cast<const uint4*>(Qg)[c];
    }

    float O[16][4];
    #pragma unroll
    for (int f = 0; f < 16; f++) {
        O[f][0] = 0.f; O[f][1] = 0.f; O[f][2] = 0.f; O[f][3] = 0.f;
    }
    float su_lo = 0.f, su_hi = 0.f;
    const int row_lo = m_base + w * 16 + g;
    const int row_hi = row_lo + 8;
    const int wrow_min = m_base + w * 16;
    const int wrow_max = wrow_min + 15;
    const int qrow = w * 16 + i8 + ((sel & 1) << 3);

    for (int kt = 0; kt < ntiles; kt++) {
        const int n0 = kt * BN;
        const int st = kt & 1;

        if (kt + 1 < ntiles) {
            const char* Kn = (const char*)(Kg + (size_t)(n0 + BN) * DH);
            const char* Vn = (const char*)(Vg + (size_t)(n0 + BN) * DH);
            #pragma unroll
            for (int i = 0; i < 4; i++) {
                int c = t + i * 256;
                int row = c >> 4, cb = (c & 15) * 16;
                cpa16(smk[st ^ 1] + sw(row, cb), Kn + c * 16);
                cpa16(smv[st ^ 1] + sw(row, cb), Vn + c * 16);
            }
            CPA_COMMIT();
            CPA_WAIT(1);
        } else {
            CPA_WAIT(0);
        }
        __syncthreads();

        if (n0 <= wrow_max) {
            // ---- S = Q K^T ----
            float S[8][4];
            #pragma unroll
            for (int f = 0; f < 8; f++) {
                S[f][0] = 0.f; S[f][1] = 0.f; S[f][2] = 0.f; S[f][3] = 0.f;
            }
            #pragma unroll
            for (int kc = 0; kc < 8; kc++) {
                uint32_t qa[4];
                // A-frag: row offset (sel&1)<<3 (in qrow), col offset (sel>>1)<<4
                ldsm4(qa, sb + SM_Q + sw(qrow, kc * 32 + ((sel >> 1) << 4)));
                // B-frag: row offset (sel>>1)<<3, col offset (sel&1)<<4
                int db = kc * 32 + ((sel & 1) << 4);
                #pragma unroll
                for (int np = 0; np < 4; np++) {
                    uint32_t kb[4];
                    int krow = np * 16 + i8 + ((sel >> 1) << 3);
                    ldsm4(kb, smk[st] + sw(krow, db));
                    mma_bf16(S[np * 2],     qa, kb[0], kb[1]);
                    mma_bf16(S[np * 2 + 1], qa, kb[2], kb[3]);
                }
            }

            // ---- u = expm1(s*scale), mask -> 0, bf16 A-fragments ----
            const bool diag = (n0 + BN - 1 > wrow_min);
            uint32_t pA[8], pB[8];
            #pragma unroll
            for (int nf = 0; nf < 8; nf++) {
                int colb = n0 + nf * 8 + 2 * j;
                float u0 = expm1s(S[nf][0] * ATTN_SCALE);
                float u1 = expm1s(S[nf][1] * ATTN_SCALE);
                float u2 = expm1s(S[nf][2] * ATTN_SCALE);
                float u3 = expm1s(S[nf][3] * ATTN_SCALE);
                if (diag) {
                    if (colb     > row_lo) u0 = 0.f;
                    if (colb + 1 > row_lo) u1 = 0.f;
                    if (colb     > row_hi) u2 = 0.f;
                    if (colb + 1 > row_hi) u3 = 0.f;
                }
                __nv_bfloat162 ba = __floats2bfloat162_rn(u0, u1);
                __nv_bfloat162 bb = __floats2bfloat162_rn(u2, u3);
                su_lo += __bfloat162float(ba.x) + __bfloat162float(ba.y);
                su_hi += __bfloat162float(bb.x) + __bfloat162float(bb.y);
                pA[nf] = *reinterpret_cast<uint32_t*>(&ba);
                pB[nf] = *reinterpret_cast<uint32_t*>(&bb);
            }

            // ---- O += u V ----
            #pragma unroll
            for (int kc2 = 0; kc2 < 4; kc2++) {
                uint32_t pa[4] = {pA[2 * kc2], pB[2 * kc2],
                                  pA[2 * kc2 + 1], pB[2 * kc2 + 1]};
                int vrow = kc2 * 16 + i8 + ((sel & 1) << 3);
                #pragma unroll
                for (int dp = 0; dp < 8; dp++) {
                    uint32_t vb[4];
                    int db = dp * 32 + ((sel >> 1) << 4);
                    ldsm4t(vb, smv[st] + sw(vrow, db));
                    mma_bf16(O[dp * 2],     pa, vb[0], vb[1]);
                    mma_bf16(O[dp * 2 + 1], pa, vb[2], vb[3]);
                }
            }
        }
        __syncthreads();   // all reads of stage st done before it is refilled
    }

    // ---- epilogue: l = (r+1) + Sigma u; stage; fused add-prefix store ----
    su_lo += __shfl_xor_sync(0xffffffffu, su_lo, 1);
    su_lo += __shfl_xor_sync(0xffffffffu, su_lo, 2);
    su_hi += __shfl_xor_sync(0xffffffffu, su_hi, 1);
    su_hi += __shfl_xor_sync(0xffffffffu, su_hi, 2);

    float* sO = reinterpret_cast<float*>(smem);
    float* sL = reinterpret_cast<float*>(smem + SM_L);
    if (j == 0) {
        sL[w * 16 + g]     = (float)(row_lo + 1) + su_lo;
        sL[w * 16 + g + 8] = (float)(row_hi + 1) + su_hi;
    }
    #pragma unroll
    for (int f = 0; f < 16; f++) {
        int colb = f * 8 + 2 * j;
        sO[(w * 16 + g)     * OSTRIDE + colb]     = O[f][0];
        sO[(w * 16 + g)     * OSTRIDE + colb + 1] = O[f][1];
        sO[(w * 16 + g + 8) * OSTRIDE + colb]     = O[f][2];
        sO[(w * 16 + g + 8) * OSTRIDE + colb + 1] = O[f][3];
    }
    __syncthreads();

    {
        int cc = t & 127, rh = t >> 7;
        const float* preb = g_vpre + ((size_t)(b * HKV + kvh) * SEQ + m_base) * DH;
        size_t obase = ((size_t)(b * SEQ + m_base)) * (HQ * DH) + (size_t)h * DH;
        #pragma unroll 4
        for (int i = 0; i < 64; i++) {
            int rr = i * 2 + rh;
            float inv = 1.0f / sL[rr];
            out[obase + (size_t)rr * (HQ * DH) + cc] =
                (sO[rr * OSTRIDE + cc] + preb[(size_t)rr * DH + cc]) * inv;
        }
    }
}

// ---------------------------------------------------------------------------
extern "C" void kernel_launch(void* const* d_in, const int* in_sizes, int n_in,
                              void* d_out, int out_size) {
    (void)in_sizes; (void)n_in; (void)out_size;
    const float* xq = (const float*)d_in[0];
    const float* xk = (const float*)d_in[1];
    const float* xv = (const float*)d_in[2];
    float* out = (float*)d_out;

    rope_fill_kernel<<<SEQ, 64>>>();
    prep_q_kernel<<<2 * SEQ * HQ / 4, 128>>>(xq);
    prep_k_kernel<<<2 * SEQ * HKV / 4, 128>>>(xk);
    prep_v_kernel<<<2 * SEQ * HKV / 8, 256>>>(xv);
    psum_kernel<<<2 * HKV * 16, DH>>>(xv);
    scan_kernel<<<2 * HKV, DH>>>();
    vpre_kernel<<<2 * HKV * 16, DH>>>(xv);

    cudaFuncSetAttribute(attn_kernel, cudaFuncAttributeMaxDynamicSharedMemorySize,
                         SMEM_BYTES);
    dim3 grid(SEQ / BM, 2 * HQ);
    attn_kernel<<<grid, NTHREADS, SMEM_BYTES>>>(out);
}

// round 8
// speedup vs baseline: 4.8454x; 1.0019x over previous
#include <cuda_runtime.h>
#include <cuda_bf16.h>
#include <math.h>
#include <stdint.h>

#define SEQ 2048
#define HQ 16
#define HKV 4
#define DH 128
#define BM 128
#define BN 64
#define NTHREADS 256

// smem layout (bytes): Q 32KB, K/V double-buffered 16KB each
#define SM_Q 0
#define SM_K0 32768
#define SM_K1 49152
#define SM_V0 65536
#define SM_V1 81920
#define SMEM_BYTES 98304
#define OSTRIDE 132
#define SM_L (BM * OSTRIDE * 4)          /* 67584 < 98304: l array after sO staging */
#define ATTN_SCALE 0.08838834764831845f  /* 1/sqrt(128) */

// ---------------------------------------------------------------------------
// Globals: bf16 prepped Q/K/V, RoPE table, fp32 causal prefix-sum of V
// ---------------------------------------------------------------------------
__device__ __align__(256) __nv_bfloat16 g_q[(size_t)2 * HQ * SEQ * DH];
__device__ __align__(256) __nv_bfloat16 g_k[(size_t)2 * HKV * SEQ * DH];
__device__ __align__(256) __nv_bfloat16 g_v[(size_t)2 * HKV * SEQ * DH];
__device__ __align__(16) float2 g_rope[SEQ * 64];
__device__ float g_psum[2 * HKV * 16 * DH];
__device__ float g_vpre[(size_t)2 * HKV * SEQ * DH];   // inclusive prefix of V

// ---------------------------------------------------------------------------
// PTX helpers (base ISA: ldmatrix, mma.sync, cp.async)
// ---------------------------------------------------------------------------
__device__ __forceinline__ uint32_t smem_to_u32(const void* p) {
    uint32_t a;
    asm("{ .reg .u64 t; cvta.to.shared.u64 t, %1; cvt.u32.u64 %0, t; }" : "=r"(a) : "l"(p));
    return a;
}
__device__ __forceinline__ void ldsm4(uint32_t* r, uint32_t addr) {
    asm volatile("ldmatrix.sync.aligned.m8n8.x4.shared.b16 {%0,%1,%2,%3}, [%4];"
                 : "=r"(r[0]), "=r"(r[1]), "=r"(r[2]), "=r"(r[3]) : "r"(addr));
}
__device__ __forceinline__ void ldsm4t(uint32_t* r, uint32_t addr) {
    asm volatile("ldmatrix.sync.aligned.m8n8.x4.trans.shared.b16 {%0,%1,%2,%3}, [%4];"
                 : "=r"(r[0]), "=r"(r[1]), "=r"(r[2]), "=r"(r[3]) : "r"(addr));
}
__device__ __forceinline__ void mma_bf16(float* c, const uint32_t* a,
                                         uint32_t b0, uint32_t b1) {
    asm volatile("mma.sync.aligned.m16n8k16.row.col.f32.bf16.bf16.f32 "
                 "{%0,%1,%2,%3}, {%4,%5,%6,%7}, {%8,%9}, {%0,%1,%2,%3};"
                 : "+f"(c[0]), "+f"(c[1]), "+f"(c[2]), "+f"(c[3])
                 : "r"(a[0]), "r"(a[1]), "r"(a[2]), "r"(a[3]), "r"(b0), "r"(b1));
}
__device__ __forceinline__ void cpa16(uint32_t dst, const void* src) {
    asm volatile("cp.async.cg.shared.global [%0], [%1], 16;" :: "r"(dst), "l"(src));
}
#define CPA_COMMIT() asm volatile("cp.async.commit_group;" ::: "memory")
#define CPA_WAIT(n)  asm volatile("cp.async.wait_group %0;" :: "n"(n) : "memory")

// Swizzled byte offset in a [rows][256B] bf16 tile (conflict-free for ldmatrix)
__device__ __forceinline__ uint32_t sw(int row, int cb) {
    return (uint32_t)(row * 256 + (cb ^ ((row & 7) << 4)));
}
// expm1 for |x| <= 0.0884: Horner degree 4, abs err < 5e-8
__device__ __forceinline__ float expm1s(float x) {
    float p = fmaf(x, 0.041666668f, 0.16666667f);
    p = fmaf(x, p, 0.5f);
    p = fmaf(x, p, 1.0f);
    return x * p;
}

// ---------------------------------------------------------------------------
// Launch 1: RoPE table (blk < SEQ) + per-chunk V column sums (psum) fused.
// ---------------------------------------------------------------------------
__global__ void rope_psum_kernel(const float* __restrict__ xv) {
    int blk = blockIdx.x;
    if (blk < SEQ) {
        int j = threadIdx.x;
        if (j < 64) {
            float inv_freq = exp2f((float)j * (-13.287712379549449f / 64.0f));
            float sn, cs;
            sincosf((float)blk * inv_freq, &sn, &cs);
            g_rope[blk * 64 + j] = make_float2(cs, sn);
        }
    } else {
        int pb = blk - SEQ;              // b*64 + kvh*16 + chunk
        int chunk = pb & 15, kvh = (pb >> 4) & 3, b = pb >> 6;
        int d = threadIdx.x;
        const float* p = xv + ((size_t)b * SEQ + chunk * 128) * (HKV * DH) + kvh * DH + d;
        float s = 0.f;
        #pragma unroll 8
        for (int i = 0; i < 128; i++) s += p[(size_t)i * (HKV * DH)];
        g_psum[pb * DH + d] = s;
    }
}

// ---------------------------------------------------------------------------
// Launch 2: all three preps fused (warp-per-row, float4, shfl-only).
// ---------------------------------------------------------------------------
__device__ __forceinline__ void prep_rows(const float* __restrict__ x,
                                          __nv_bfloat16* __restrict__ y,
                                          int H, int blk) {
    const int wid = threadIdx.x >> 5, lane = threadIdx.x & 31;
    const int idx = blk * 4 + wid;       // b*SEQ*H + s*H + h
    const int h = idx % H;
    const int s = (idx / H) % SEQ;
    const int b = idx / (H * SEQ);

    float4 v = reinterpret_cast<const float4*>(x + (size_t)idx * DH)[lane];
    float ss = v.x * v.x + v.y * v.y + v.z * v.z + v.w * v.w;
    #pragma unroll
    for (int o = 16; o; o >>= 1) ss += __shfl_xor_sync(0xffffffffu, ss, o);
    float scale = 1.0f / fmaxf(sqrtf(ss), 1e-6f);

    float px = __shfl_xor_sync(0xffffffffu, v.x, 16);
    float py = __shfl_xor_sync(0xffffffffu, v.y, 16);
    float pz = __shfl_xor_sync(0xffffffffu, v.z, 16);
    float pw = __shfl_xor_sync(0xffffffffu, v.w, 16);

    int j0 = 4 * (lane & 15);
    const float4* rp = reinterpret_cast<const float4*>(g_rope + s * 64 + j0);
    float4 r01 = rp[0];   // cos0,sin0,cos1,sin1
    float4 r23 = rp[1];

    float o0, o1, o2, o3;
    if (lane < 16) {       // y1 = x1*cos + x2*sin
        o0 = (v.x * r01.x + px * r01.y) * scale;
        o1 = (v.y * r01.z + py * r01.w) * scale;
        o2 = (v.z * r23.x + pz * r23.y) * scale;
        o3 = (v.w * r23.z + pw * r23.w) * scale;
    } else {               // y2 = x2*cos - x1*sin
        o0 = (v.x * r01.x - px * r01.y) * scale;
        o1 = (v.y * r01.z - py * r01.w) * scale;
        o2 = (v.z * r23.x - pz * r23.y) * scale;
        o3 = (v.w * r23.z - pw * r23.w) * scale;
    }
    __nv_bfloat162 ba = __floats2bfloat162_rn(o0, o1);
    __nv_bfloat162 bb = __floats2bfloat162_rn(o2, o3);
    uint2 pk = make_uint2(*reinterpret_cast<uint32_t*>(&ba),
                          *reinterpret_cast<uint32_t*>(&bb));
    *reinterpret_cast<uint2*>(y + (((size_t)(b * H + h)) * SEQ + s) * DH + 4 * lane) = pk;
}

__global__ void prep_all_kernel(const float* __restrict__ xq,
                                const float* __restrict__ xk,
                                const float* __restrict__ xv) {
    int blk = blockIdx.x;
    if (blk < 16384) {
        prep_rows(xq, g_q, HQ, blk);
    } else if (blk < 16384 + 4096) {
        prep_rows(xk, g_k, HKV, blk - 16384);
    } else {
        const int wid = threadIdx.x >> 5, lane = threadIdx.x & 31;
        const int idx = (blk - 20480) * 4 + wid;   // b*SEQ*HKV + s*HKV + h
        const int h = idx % HKV;
        const int s = (idx / HKV) % SEQ;
        const int b = idx / (HKV * SEQ);
        float4 v = reinterpret_cast<const float4*>(xv + (size_t)idx * DH)[lane];
        __nv_bfloat162 ba = __floats2bfloat162_rn(v.x, v.y);
        __nv_bfloat162 bb = __floats2bfloat162_rn(v.z, v.w);
        uint2 pk = make_uint2(*reinterpret_cast<uint32_t*>(&ba),
                              *reinterpret_cast<uint32_t*>(&bb));
        *reinterpret_cast<uint2*>(g_v + (((size_t)(b * HKV + h)) * SEQ + s) * DH + 4 * lane) = pk;
    }
}

// ---------------------------------------------------------------------------
// Launch 3: inclusive prefix of V; chunk offset derived from g_psum inline.
// ---------------------------------------------------------------------------
__global__ void vpre_kernel(const float* __restrict__ xv) {
    int blk = blockIdx.x;                // b*64 + kvh*16 + chunk
    int chunk = blk & 15, kvh = (blk >> 4) & 3, b = blk >> 6;
    int d = threadIdx.x;
    float acc = 0.f;
    int base = blk - chunk;
    for (int c = 0; c < chunk; c++) acc += g_psum[(base + c) * DH + d];
    const float* p = xv + ((size_t)b * SEQ + chunk * 128) * (HKV * DH) + kvh * DH + d;
    float* o = g_vpre + ((size_t)(b * HKV + kvh) * SEQ + chunk * 128) * DH + d;
    #pragma unroll 8
    for (int i = 0; i < 128; i++) {
        acc += p[(size_t)i * (HKV * DH)];
        o[(size_t)i * DH] = acc;
    }
}

// ---------------------------------------------------------------------------
// Launch 4: bf16 mma.sync flash attention, p = 1 + u, cp.async double-buffer.
// CTA: 256 thr (8 warps), BM=128 q-rows (16/warp), BN=64 keys/tile, 2 CTAs/SM.
// u-conversion fused into the PV loop (S dies progressively; no pA/pB arrays).
// ---------------------------------------------------------------------------
__global__ void __launch_bounds__(NTHREADS, 2)
attn_kernel(float* __restrict__ out) {
    extern __shared__ char smem[];
    const uint32_t sb = smem_to_u32(smem);
    const int t = threadIdx.x;
    const int w = t >> 5, lane = t & 31;
    const int g = lane >> 2, j = lane & 3;
    const int i8 = lane & 7, sel = lane >> 3;

    const int mt = (int)gridDim.x - 1 - (int)blockIdx.x;   // heavy tiles first
    const int bh = blockIdx.y;
    const int b = bh >> 4, h = bh & 15;
    const int kvh = h >> 2;
    const int m_base = mt * BM;
    const int ntiles = 2 * mt + 2;

    const __nv_bfloat16* Qg = g_q + ((size_t)bh * SEQ + m_base) * DH;
    const __nv_bfloat16* Kg = g_k + ((size_t)(b * HKV + kvh) * SEQ) * DH;
    const __nv_bfloat16* Vg = g_v + ((size_t)(b * HKV + kvh) * SEQ) * DH;

    const uint32_t smk[2] = {sb + SM_K0, sb + SM_K1};
    const uint32_t smv[2] = {sb + SM_V0, sb + SM_V1};

    // prologue: async-issue K/V tile 0, then load Q while it flies
    {
        #pragma unroll
        for (int i = 0; i < 4; i++) {
            int c = t + i * 256;
            int row = c >> 4, cb = (c & 15) * 16;
            cpa16(smk[0] + sw(row, cb), (const char*)Kg + c * 16);
            cpa16(smv[0] + sw(row, cb), (const char*)Vg + c * 16);
        }
        CPA_COMMIT();
    }
    #pragma unroll
    for (int i = 0; i < 8; i++) {
        int c = t + i * 256;
        int row = c >> 4, cb = (c & 15) * 16;
        *reinterpret_cast<uint4*>(smem + SM_Q + sw(row, cb)) =
            reinterpret_cast<const uint4*>(Qg)[c];
    }

    float O[16][4];
    #pragma unroll
    for (int f = 0; f < 16; f++) {
        O[f][0] = 0.f; O[f][1] = 0.f; O[f][2] = 0.f; O[f][3] = 0.f;
    }
    float su_lo = 0.f, su_hi = 0.f;
    const int row_lo = m_base + w * 16 + g;
    const int row_hi = row_lo + 8;
    const int wrow_min = m_base + w * 16;
    const int wrow_max = wrow_min + 15;
    const int qrow = w * 16 + i8 + ((sel & 1) << 3);

    for (int kt = 0; kt < ntiles; kt++) {
        const int n0 = kt * BN;
        const int st = kt & 1;

        if (kt + 1 < ntiles) {
            const char* Kn = (const char*)(Kg + (size_t)(n0 + BN) * DH);
            const char* Vn = (const char*)(Vg + (size_t)(n0 + BN) * DH);
            #pragma unroll
            for (int i = 0; i < 4; i++) {
                int c = t + i * 256;
                int row = c >> 4, cb = (c & 15) * 16;
                cpa16(smk[st ^ 1] + sw(row, cb), Kn + c * 16);
                cpa16(smv[st ^ 1] + sw(row, cb), Vn + c * 16);
            }
            CPA_COMMIT();
            CPA_WAIT(1);
        } else {
            CPA_WAIT(0);
        }
        __syncthreads();

        if (n0 <= wrow_max) {
            // ---- S = Q K^T ----
            float S[8][4];
            #pragma unroll
            for (int f = 0; f < 8; f++) {
                S[f][0] = 0.f; S[f][1] = 0.f; S[f][2] = 0.f; S[f][3] = 0.f;
            }
            #pragma unroll
            for (int kc = 0; kc < 8; kc++) {
                uint32_t qa[4];
                // A-frag: row offset (sel&1)<<3 (in qrow), col offset (sel>>1)<<4
                ldsm4(qa, sb + SM_Q + sw(qrow, kc * 32 + ((sel >> 1) << 4)));
                // B-frag: row offset (sel>>1)<<3, col offset (sel&1)<<4
                int db = kc * 32 + ((sel & 1) << 4);
                #pragma unroll
                for (int np = 0; np < 4; np++) {
                    uint32_t kb[4];
                    int krow = np * 16 + i8 + ((sel >> 1) << 3);
                    ldsm4(kb, smk[st] + sw(krow, db));
                    mma_bf16(S[np * 2],     qa, kb[0], kb[1]);
                    mma_bf16(S[np * 2 + 1], qa, kb[2], kb[3]);
                }
            }

            // ---- O += u V, converting S -> u bf16 fragments just-in-time ----
            const bool diag = (n0 + BN - 1 > wrow_min);
            #pragma unroll
            for (int kc2 = 0; kc2 < 4; kc2++) {
                uint32_t pa[4];
                #pragma unroll
                for (int q2 = 0; q2 < 2; q2++) {
                    const int nf = 2 * kc2 + q2;
                    const int colb = n0 + nf * 8 + 2 * j;
                    float u0 = expm1s(S[nf][0] * ATTN_SCALE);
                    float u1 = expm1s(S[nf][1] * ATTN_SCALE);
                    float u2 = expm1s(S[nf][2] * ATTN_SCALE);
                    float u3 = expm1s(S[nf][3] * ATTN_SCALE);
                    if (diag) {
                        if (colb     > row_lo) u0 = 0.f;
                        if (colb + 1 > row_lo) u1 = 0.f;
                        if (colb     > row_hi) u2 = 0.f;
                        if (colb + 1 > row_hi) u3 = 0.f;
                    }
                    __nv_bfloat162 ba = __floats2bfloat162_rn(u0, u1);
                    __nv_bfloat162 bb = __floats2bfloat162_rn(u2, u3);
                    su_lo += __bfloat162float(ba.x) + __bfloat162float(ba.y);
                    su_hi += __bfloat162float(bb.x) + __bfloat162float(bb.y);
                    pa[2 * q2]     = *reinterpret_cast<uint32_t*>(&ba);
                    pa[2 * q2 + 1] = *reinterpret_cast<uint32_t*>(&bb);
                }
                int vrow = kc2 * 16 + i8 + ((sel & 1) << 3);
                #pragma unroll
                for (int dp = 0; dp < 8; dp++) {
                    uint32_t vb[4];
                    int db = dp * 32 + ((sel >> 1) << 4);
                    ldsm4t(vb, smv[st] + sw(vrow, db));
                    mma_bf16(O[dp * 2],     pa, vb[0], vb[1]);
                    mma_bf16(O[dp * 2 + 1], pa, vb[2], vb[3]);
                }
            }
        }
        __syncthreads();   // all reads of stage st done before it is refilled
    }

    // ---- epilogue: l = (r+1) + Sigma u; stage; fused add-prefix store ----
    su_lo += __shfl_xor_sync(0xffffffffu, su_lo, 1);
    su_lo += __shfl_xor_sync(0xffffffffu, su_lo, 2);
    su_hi += __shfl_xor_sync(0xffffffffu, su_hi, 1);
    su_hi += __shfl_xor_sync(0xffffffffu, su_hi, 2);

    float* sO = reinterpret_cast<float*>(smem);
    float* sL = reinterpret_cast<float*>(smem + SM_L);
    if (j == 0) {
        sL[w * 16 + g]     = (float)(row_lo + 1) + su_lo;
        sL[w * 16 + g + 8] = (float)(row_hi + 1) + su_hi;
    }
    #pragma unroll
    for (int f = 0; f < 16; f++) {
        int colb = f * 8 + 2 * j;
        sO[(w * 16 + g)     * OSTRIDE + colb]     = O[f][0];
        sO[(w * 16 + g)     * OSTRIDE + colb + 1] = O[f][1];
        sO[(w * 16 + g + 8) * OSTRIDE + colb]     = O[f][2];
        sO[(w * 16 + g + 8) * OSTRIDE + colb + 1] = O[f][3];
    }
    __syncthreads();

    {
        int cc = t & 127, rh = t >> 7;
        const float* preb = g_vpre + ((size_t)(b * HKV + kvh) * SEQ + m_base) * DH;
        size_t obase = ((size_t)(b * SEQ + m_base)) * (HQ * DH) + (size_t)h * DH;
        #pragma unroll 4
        for (int i = 0; i < 64; i++) {
            int rr = i * 2 + rh;
            float inv = 1.0f / sL[rr];
            out[obase + (size_t)rr * (HQ * DH) + cc] =
                (sO[rr * OSTRIDE + cc] + preb[(size_t)rr * DH + cc]) * inv;
        }
    }
}

// ---------------------------------------------------------------------------
extern "C" void kernel_launch(void* const* d_in, const int* in_sizes, int n_in,
                              void* d_out, int out_size) {
    (void)in_sizes; (void)n_in; (void)out_size;
    const float* xq = (const float*)d_in[0];
    const float* xk = (const float*)d_in[1];
    const float* xv = (const float*)d_in[2];
    float* out = (float*)d_out;

    rope_psum_kernel<<<SEQ + 128, 128>>>(xv);
    prep_all_kernel<<<16384 + 4096 + 4096, 128>>>(xq, xk, xv);
    vpre_kernel<<<128, DH>>>(xv);

    cudaFuncSetAttribute(attn_kernel, cudaFuncAttributeMaxDynamicSharedMemorySize,
                         SMEM_BYTES);
    dim3 grid(SEQ / BM, 2 * HQ);
    attn_kernel<<<grid, NTHREADS, SMEM_BYTES>>>(out);
}

// round 10
// speedup vs baseline: 5.6671x; 1.1696x over previous
#include <cuda_runtime.h>
#include <cuda_bf16.h>
#include <math.h>
#include <stdint.h>

#define SEQ 2048
#define HQ 16
#define HKV 4
#define DH 128
#define BM 128
#define BN 64
#define NTHREADS 256

// smem layout (bytes): Q 32KB, K/V double-buffered 16KB each
#define SM_Q 0
#define SM_K0 32768
#define SM_K1 49152
#define SM_V0 65536
#define SM_V1 81920
#define SMEM_BYTES 98304

// expm1(c*s) Horner coefficients in s, c = 1/sqrt(128)
#define EC1 0.08838834764831845f     /* c       */
#define EC2 0.00390625f              /* c^2/2   */
#define EC3 1.1508899433374798e-4f   /* c^3/6   */
#define EC4 2.543131510416667e-6f    /* c^4/24  */

// ---------------------------------------------------------------------------
// Globals: bf16 prepped Q/K/V, RoPE table, fp32 causal prefix-sum of V
// ---------------------------------------------------------------------------
__device__ __align__(256) __nv_bfloat16 g_q[(size_t)2 * HQ * SEQ * DH];
__device__ __align__(256) __nv_bfloat16 g_k[(size_t)2 * HKV * SEQ * DH];
__device__ __align__(256) __nv_bfloat16 g_v[(size_t)2 * HKV * SEQ * DH];
__device__ __align__(16) float2 g_rope[SEQ * 64];
__device__ float g_psum[2 * HKV * 16 * DH];
__device__ float g_vpre[(size_t)2 * HKV * SEQ * DH];   // inclusive prefix of V

// ---------------------------------------------------------------------------
// PTX helpers (base ISA: ldmatrix, mma.sync, cp.async)
// ---------------------------------------------------------------------------
__device__ __forceinline__ uint32_t smem_to_u32(const void* p) {
    uint32_t a;
    asm("{ .reg .u64 t; cvta.to.shared.u64 t, %1; cvt.u32.u64 %0, t; }" : "=r"(a) : "l"(p));
    return a;
}
__device__ __forceinline__ void ldsm4(uint32_t* r, uint32_t addr) {
    asm volatile("ldmatrix.sync.aligned.m8n8.x4.shared.b16 {%0,%1,%2,%3}, [%4];"
                 : "=r"(r[0]), "=r"(r[1]), "=r"(r[2]), "=r"(r[3]) : "r"(addr));
}
__device__ __forceinline__ void ldsm4t(uint32_t* r, uint32_t addr) {
    asm volatile("ldmatrix.sync.aligned.m8n8.x4.trans.shared.b16 {%0,%1,%2,%3}, [%4];"
                 : "=r"(r[0]), "=r"(r[1]), "=r"(r[2]), "=r"(r[3]) : "r"(addr));
}
__device__ __forceinline__ void mma_bf16(float* c, const uint32_t* a,
                                         uint32_t b0, uint32_t b1) {
    asm volatile("mma.sync.aligned.m16n8k16.row.col.f32.bf16.bf16.f32 "
                 "{%0,%1,%2,%3}, {%4,%5,%6,%7}, {%8,%9}, {%0,%1,%2,%3};"
                 : "+f"(c[0]), "+f"(c[1]), "+f"(c[2]), "+f"(c[3])
                 : "r"(a[0]), "r"(a[1]), "r"(a[2]), "r"(a[3]), "r"(b0), "r"(b1));
}
__device__ __forceinline__ void cpa16(uint32_t dst, const void* src) {
    asm volatile("cp.async.cg.shared.global [%0], [%1], 16;" :: "r"(dst), "l"(src));
}
#define CPA_COMMIT() asm volatile("cp.async.commit_group;" ::: "memory")
#define CPA_WAIT(n)  asm volatile("cp.async.wait_group %0;" :: "n"(n) : "memory")

// Swizzled byte offset in a [rows][256B] bf16 tile (conflict-free for ldmatrix)
__device__ __forceinline__ uint32_t sw(int row, int cb) {
    return (uint32_t)(row * 256 + (cb ^ ((row & 7) << 4)));
}
// u = expm1(c*s) for |c*s| <= 0.0884 via Horner in s (scale folded into coeffs)
__device__ __forceinline__ float expm1cs(float s) {
    float p = fmaf(s, EC4, EC3);
    p = fmaf(s, p, EC2);
    p = fmaf(s, p, EC1);
    return s * p;
}

// ---------------------------------------------------------------------------
// Launch 1: RoPE table (blk < SEQ) + per-chunk V column sums (psum) fused.
// ---------------------------------------------------------------------------
__global__ void rope_psum_kernel(const float* __restrict__ xv) {
    int blk = blockIdx.x;
    if (blk < SEQ) {
        int j = threadIdx.x;
        if (j < 64) {
            float inv_freq = exp2f((float)j * (-13.287712379549449f / 64.0f));
            float sn, cs;
            sincosf((float)blk * inv_freq, &sn, &cs);
            g_rope[blk * 64 + j] = make_float2(cs, sn);
        }
    } else {
        int pb = blk - SEQ;              // b*64 + kvh*16 + chunk
        int chunk = pb & 15, kvh = (pb >> 4) & 3, b = pb >> 6;
        int d = threadIdx.x;
        const float* p = xv + ((size_t)b * SEQ + chunk * 128) * (HKV * DH) + kvh * DH + d;
        float s = 0.f;
        #pragma unroll 8
        for (int i = 0; i < 128; i++) s += p[(size_t)i * (HKV * DH)];
        g_psum[pb * DH + d] = s;
    }
}

// ---------------------------------------------------------------------------
// Launch 2: all three preps fused (warp-per-row, float4, shfl-only).
// ---------------------------------------------------------------------------
__device__ __forceinline__ void prep_rows(const float* __restrict__ x,
                                          __nv_bfloat16* __restrict__ y,
                                          int H, int blk) {
    const int wid = threadIdx.x >> 5, lane = threadIdx.x & 31;
    const int idx = blk * 4 + wid;       // b*SEQ*H + s*H + h
    const int h = idx % H;
    const int s = (idx / H) % SEQ;
    const int b = idx / (H * SEQ);

    float4 v = reinterpret_cast<const float4*>(x + (size_t)idx * DH)[lane];
    float ss = v.x * v.x + v.y * v.y + v.z * v.z + v.w * v.w;
    #pragma unroll
    for (int o = 16; o; o >>= 1) ss += __shfl_xor_sync(0xffffffffu, ss, o);
    float scale = 1.0f / fmaxf(sqrtf(ss), 1e-6f);

    float px = __shfl_xor_sync(0xffffffffu, v.x, 16);
    float py = __shfl_xor_sync(0xffffffffu, v.y, 16);
    float pz = __shfl_xor_sync(0xffffffffu, v.z, 16);
    float pw = __shfl_xor_sync(0xffffffffu, v.w, 16);

    int j0 = 4 * (lane & 15);
    const float4* rp = reinterpret_cast<const float4*>(g_rope + s * 64 + j0);
    float4 r01 = rp[0];   // cos0,sin0,cos1,sin1
    float4 r23 = rp[1];

    float o0, o1, o2, o3;
    if (lane < 16) {       // y1 = x1*cos + x2*sin
        o0 = (v.x * r01.x + px * r01.y) * scale;
        o1 = (v.y * r01.z + py * r01.w) * scale;
        o2 = (v.z * r23.x + pz * r23.y) * scale;
        o3 = (v.w * r23.z + pw * r23.w) * scale;
    } else {               // y2 = x2*cos - x1*sin
        o0 = (v.x * r01.x - px * r01.y) * scale;
        o1 = (v.y * r01.z - py * r01.w) * scale;
        o2 = (v.z * r23.x - pz * r23.y) * scale;
        o3 = (v.w * r23.z - pw * r23.w) * scale;
    }
    __nv_bfloat162 ba = __floats2bfloat162_rn(o0, o1);
    __nv_bfloat162 bb = __floats2bfloat162_rn(o2, o3);
    uint2 pk = make_uint2(*reinterpret_cast<uint32_t*>(&ba),
                          *reinterpret_cast<uint32_t*>(&bb));
    *reinterpret_cast<uint2*>(y + (((size_t)(b * H + h)) * SEQ + s) * DH + 4 * lane) = pk;
}

__global__ void prep_all_kernel(const float* __restrict__ xq,
                                const float* __restrict__ xk,
                                const float* __restrict__ xv) {
    int blk = blockIdx.x;
    if (blk < 16384) {
        prep_rows(xq, g_q, HQ, blk);
    } else if (blk < 16384 + 4096) {
        prep_rows(xk, g_k, HKV, blk - 16384);
    } else {
        const int wid = threadIdx.x >> 5, lane = threadIdx.x & 31;
        const int idx = (blk - 20480) * 4 + wid;   // b*SEQ*HKV + s*HKV + h
        const int h = idx % HKV;
        const int s = (idx / HKV) % SEQ;
        const int b = idx / (HKV * SEQ);
        float4 v = reinterpret_cast<const float4*>(xv + (size_t)idx * DH)[lane];
        __nv_bfloat162 ba = __floats2bfloat162_rn(v.x, v.y);
        __nv_bfloat162 bb = __floats2bfloat162_rn(v.z, v.w);
        uint2 pk = make_uint2(*reinterpret_cast<uint32_t*>(&ba),
                              *reinterpret_cast<uint32_t*>(&bb));
        *reinterpret_cast<uint2*>(g_v + (((size_t)(b * HKV + h)) * SEQ + s) * DH + 4 * lane) = pk;
    }
}

// ---------------------------------------------------------------------------
// Launch 3: inclusive prefix of V; chunk offset derived from g_psum inline.
// ---------------------------------------------------------------------------
__global__ void vpre_kernel(const float* __restrict__ xv) {
    int blk = blockIdx.x;                // b*64 + kvh*16 + chunk
    int chunk = blk & 15, kvh = (blk >> 4) & 3, b = blk >> 6;
    int d = threadIdx.x;
    float acc = 0.f;
    int base = blk - chunk;
    for (int c = 0; c < chunk; c++) acc += g_psum[(base + c) * DH + d];
    const float* p = xv + ((size_t)b * SEQ + chunk * 128) * (HKV * DH) + kvh * DH + d;
    float* o = g_vpre + ((size_t)(b * HKV + kvh) * SEQ + chunk * 128) * DH + d;
    #pragma unroll 8
    for (int i = 0; i < 128; i++) {
        acc += p[(size_t)i * (HKV * DH)];
        o[(size_t)i * DH] = acc;
    }
}

// ---------------------------------------------------------------------------
// Launch 4: bf16 mma.sync flash attention, p = 1 + u.
// Single barrier per tile: prefetch of kt+1 issued between QK and PV of kt.
// Direct-from-register epilogue (no smem staging).
// ---------------------------------------------------------------------------
__global__ void __launch_bounds__(NTHREADS, 2)
attn_kernel(float* __restrict__ out) {
    extern __shared__ char smem[];
    const uint32_t sb = smem_to_u32(smem);
    const int t = threadIdx.x;
    const int w = t >> 5, lane = t & 31;
    const int g = lane >> 2, j = lane & 3;
    const int i8 = lane & 7, sel = lane >> 3;

    const int mt = (int)gridDim.x - 1 - (int)blockIdx.x;   // heavy tiles first
    const int bh = blockIdx.y;
    const int b = bh >> 4, h = bh & 15;
    const int kvh = h >> 2;
    const int m_base = mt * BM;
    const int ntiles = 2 * mt + 2;

    const __nv_bfloat16* Qg = g_q + ((size_t)bh * SEQ + m_base) * DH;
    const __nv_bfloat16* Kg = g_k + ((size_t)(b * HKV + kvh) * SEQ) * DH;
    const __nv_bfloat16* Vg = g_v + ((size_t)(b * HKV + kvh) * SEQ) * DH;

    const uint32_t smk[2] = {sb + SM_K0, sb + SM_K1};
    const uint32_t smv[2] = {sb + SM_V0, sb + SM_V1};

    // prologue: async-issue K/V tile 0, then load Q while it flies
    {
        #pragma unroll
        for (int i = 0; i < 4; i++) {
            int c = t + i * 256;
            int row = c >> 4, cb = (c & 15) * 16;
            cpa16(smk[0] + sw(row, cb), (const char*)Kg + c * 16);
            cpa16(smv[0] + sw(row, cb), (const char*)Vg + c * 16);
        }
        CPA_COMMIT();
    }
    #pragma unroll
    for (int i = 0; i < 8; i++) {
        int c = t + i * 256;
        int row = c >> 4, cb = (c & 15) * 16;
        *reinterpret_cast<uint4*>(smem + SM_Q + sw(row, cb)) =
            reinterpret_cast<const uint4*>(Qg)[c];
    }

    float O[16][4];
    #pragma unroll
    for (int f = 0; f < 16; f++) {
        O[f][0] = 0.f; O[f][1] = 0.f; O[f][2] = 0.f; O[f][3] = 0.f;
    }
    float su_lo = 0.f, su_hi = 0.f;
    const int row_lo = m_base + w * 16 + g;
    const int row_hi = row_lo + 8;
    const int wrow_min = m_base + w * 16;
    const int wrow_max = wrow_min + 15;
    const int qrow = w * 16 + i8 + ((sel & 1) << 3);

    for (int kt = 0; kt < ntiles; kt++) {
        const int n0 = kt * BN;
        const int st = kt & 1;

        // the single group in flight carries tile kt (committed prev iter/prologue)
        CPA_WAIT(0);
        __syncthreads();

        const bool work = (n0 <= wrow_max);
        float S[8][4];
        if (work) {
            // ---- S = Q K^T ----
            #pragma unroll
            for (int f = 0; f < 8; f++) {
                S[f][0] = 0.f; S[f][1] = 0.f; S[f][2] = 0.f; S[f][3] = 0.f;
            }
            #pragma unroll
            for (int kc = 0; kc < 8; kc++) {
                uint32_t qa[4];
                // A-frag: row offset (sel&1)<<3 (in qrow), col offset (sel>>1)<<4
                ldsm4(qa, sb + SM_Q + sw(qrow, kc * 32 + ((sel >> 1) << 4)));
                // B-frag: row offset (sel>>1)<<3, col offset (sel&1)<<4
                int db = kc * 32 + ((sel & 1) << 4);
                #pragma unroll
                for (int np = 0; np < 4; np++) {
                    uint32_t kb[4];
                    int krow = np * 16 + i8 + ((sel >> 1) << 3);
                    ldsm4(kb, smk[st] + sw(krow, db));
                    mma_bf16(S[np * 2],     qa, kb[0], kb[1]);
                    mma_bf16(S[np * 2 + 1], qa, kb[2], kb[3]);
                }
            }
        }

        // ---- prefetch tile kt+1 into stage st^1 (safe: st^1 last read kt-1,
        //      all warps passed the barrier above after finishing kt-1) ----
        if (kt + 1 < ntiles) {
            const char* Kn = (const char*)(Kg + (size_t)(n0 + BN) * DH);
            const char* Vn = (const char*)(Vg + (size_t)(n0 + BN) * DH);
            #pragma unroll
            for (int i = 0; i < 4; i++) {
                int c = t + i * 256;
                int row = c >> 4, cb = (c & 15) * 16;
                cpa16(smk[st ^ 1] + sw(row, cb), Kn + c * 16);
                cpa16(smv[st ^ 1] + sw(row, cb), Vn + c * 16);
            }
            CPA_COMMIT();
        }

        if (work) {
            // ---- O += u V, converting S -> u bf16 fragments just-in-time ----
            const bool diag = (n0 + BN - 1 > wrow_min);
            #pragma unroll
            for (int kc2 = 0; kc2 < 4; kc2++) {
                uint32_t pa[4];
                #pragma unroll
                for (int q2 = 0; q2 < 2; q2++) {
                    const int nf = 2 * kc2 + q2;
                    const int colb = n0 + nf * 8 + 2 * j;
                    float u0 = expm1cs(S[nf][0]);
                    float u1 = expm1cs(S[nf][1]);
                    float u2 = expm1cs(S[nf][2]);
                    float u3 = expm1cs(S[nf][3]);
                    if (diag) {
                        if (colb     > row_lo) u0 = 0.f;
                        if (colb + 1 > row_lo) u1 = 0.f;
                        if (colb     > row_hi) u2 = 0.f;
                        if (colb + 1 > row_hi) u3 = 0.f;
                    }
                    su_lo += u0 + u1;          // fp32 pre-rounding (err ~3e-6 rel)
                    su_hi += u2 + u3;
                    __nv_bfloat162 ba = __floats2bfloat162_rn(u0, u1);
                    __nv_bfloat162 bb = __floats2bfloat162_rn(u2, u3);
                    pa[2 * q2]     = *reinterpret_cast<uint32_t*>(&ba);
                    pa[2 * q2 + 1] = *reinterpret_cast<uint32_t*>(&bb);
                }
                int vrow = kc2 * 16 + i8 + ((sel & 1) << 3);
                #pragma unroll
                for (int dp = 0; dp < 8; dp++) {
                    uint32_t vb[4];
                    int db = dp * 32 + ((sel >> 1) << 4);
                    ldsm4t(vb, smv[st] + sw(vrow, db));
                    mma_bf16(O[dp * 2],     pa, vb[0], vb[1]);
                    mma_bf16(O[dp * 2 + 1], pa, vb[2], vb[3]);
                }
            }
        }
    }

    // ---- epilogue: l = (r+1) + Sigma u; direct (O + vpre)/l stores ----
    su_lo += __shfl_xor_sync(0xffffffffu, su_lo, 1);
    su_lo += __shfl_xor_sync(0xffffffffu, su_lo, 2);
    su_hi += __shfl_xor_sync(0xffffffffu, su_hi, 1);
    su_hi += __shfl_xor_sync(0xffffffffu, su_hi, 2);
    const float inv_lo = 1.0f / ((float)(row_lo + 1) + su_lo);
    const float inv_hi = 1.0f / ((float)(row_hi + 1) + su_hi);

    const float* pre = g_vpre + ((size_t)(b * HKV + kvh) * SEQ + row_lo) * DH;
    float* o0 = out + ((size_t)(b * SEQ + row_lo)) * (HQ * DH) + (size_t)h * DH;
    #pragma unroll
    for (int f = 0; f < 16; f++) {
        int colb = f * 8 + 2 * j;
        float2 plo = *reinterpret_cast<const float2*>(pre + colb);
        float2 phi = *reinterpret_cast<const float2*>(pre + 8 * DH + colb);
        float2 rlo = make_float2((O[f][0] + plo.x) * inv_lo,
                                 (O[f][1] + plo.y) * inv_lo);
        float2 rhi = make_float2((O[f][2] + phi.x) * inv_hi,
                                 (O[f][3] + phi.y) * inv_hi);
        *reinterpret_cast<float2*>(o0 + colb) = rlo;
        *reinterpret_cast<float2*>(o0 + (size_t)8 * (HQ * DH) + colb) = rhi;
    }
}

// ---------------------------------------------------------------------------
extern "C" void kernel_launch(void* const* d_in, const int* in_sizes, int n_in,
                              void* d_out, int out_size) {
    (void)in_sizes; (void)n_in; (void)out_size;
    const float* xq = (const float*)d_in[0];
    const float* xk = (const float*)d_in[1];
    const float* xv = (const float*)d_in[2];
    float* out = (float*)d_out;

    rope_psum_kernel<<<SEQ + 128, 128>>>(xv);
    prep_all_kernel<<<16384 + 4096 + 4096, 128>>>(xq, xk, xv);
    vpre_kernel<<<128, DH>>>(xv);

    cudaFuncSetAttribute(attn_kernel, cudaFuncAttributeMaxDynamicSharedMemorySize,
                         SMEM_BYTES);
    dim3 grid(SEQ / BM, 2 * HQ);
    attn_kernel<<<grid, NTHREADS, SMEM_BYTES>>>(out);
}